// round 8
// baseline (speedup 1.0000x reference)
#include <cuda_runtime.h>
#include <cuda_bf16.h>
#include <math.h>
#include <stdint.h>

// ---------------- problem constants ----------------
#define Nn   100000
#define Ee   1600000
#define EN   (Ee + Nn)          // edges incl. self loops = 1,700,000
#define FIN  512
#define FHID 64
#define FOUT 40
#define NEG_SLOPE 0.2f
#define TILES ((Nn + 127) / 128)   // 782

// ---------------- device scratch (no dynamic alloc allowed) ----------------
__device__ __align__(16) float g_h1 [(size_t)Nn * FHID];   // x@W1
__device__ __align__(16) float g_h2 [(size_t)Nn * FOUT];   // fused layer1-out @ W2
__device__ float g_as1[Nn], g_ad1[Nn];
__device__ float g_as2[Nn], g_ad2[Nn];
__device__ int   g_cnt[Nn];
__device__ int   g_off[Nn + 1];
__device__ int   g_cursor[Nn];
__device__ int   g_csr_src[EN];
__device__ int   g_is64;
// W1 pre-converted: [n][k] K-contiguous bf16 hi/lo, stored as uint2 = 4 bf16 along k
__device__ __align__(16) uint2 g_wbh2[64 * 128];
__device__ __align__(16) uint2 g_wbl2[64 * 128];

#define SCAN_BS   1024
#define SCAN_NBLK ((Nn + SCAN_BS - 1) / SCAN_BS)   // 98
__device__ int g_partials[SCAN_NBLK];

__device__ __forceinline__ uint32_t pack_bf2(float a, float b) {
    __nv_bfloat162 t = __floats2bfloat162_rn(a, b);
    return *reinterpret_cast<uint32_t*>(&t);
}
__device__ __forceinline__ float leaky(float z) { return z > 0.f ? z : NEG_SLOPE * z; }

// mma.sync m16n8k16 row.col f32.bf16.bf16.f32 (sm_80+ PTX, valid on sm_100)
#define MMA_BF16(c, a, b) \
    asm volatile("mma.sync.aligned.m16n8k16.row.col.f32.bf16.bf16.f32 " \
        "{%0,%1,%2,%3}, {%4,%5,%6,%7}, {%8,%9}, {%0,%1,%2,%3};" \
        : "+f"((c)[0]), "+f"((c)[1]), "+f"((c)[2]), "+f"((c)[3]) \
        : "r"((a)[0]), "r"((a)[1]), "r"((a)[2]), "r"((a)[3]), "r"((b)[0]), "r"((b)[1]))

// ---------------- streams for fork-join overlap (created once, pre-main) ----
static cudaStream_t g_s2;
static cudaEvent_t  g_evFork, g_evJoin;
static struct _StreamInit {
    _StreamInit() {
        cudaStreamCreateWithFlags(&g_s2, cudaStreamNonBlocking);
        cudaEventCreateWithFlags(&g_evFork, cudaEventDisableTiming);
        cudaEventCreateWithFlags(&g_evJoin, cudaEventDisableTiming);
    }
} g_streamInit;

// ---------------- dtype detection ----------------
__global__ void k_detect(const int2* __restrict__ p) {
    __shared__ int flag;
    if (threadIdx.x == 0) flag = 0;
    __syncthreads();
    int nz = 0;
    for (int i = threadIdx.x; i < 1024; i += blockDim.x)
        if (p[i].y != 0) nz = 1;
    if (nz) atomicOr(&flag, 1);
    __syncthreads();
    if (threadIdx.x == 0) g_is64 = (flag == 0) ? 1 : 0;
}

__device__ __forceinline__ int load_edge(const void* ei, long long idx, int is64) {
    int v;
    if (is64) v = (int)((const long long*)ei)[idx];
    else      v = ((const int*)ei)[idx];
    v = v < 0 ? 0 : (v >= Nn ? Nn - 1 : v);
    return v;
}

// ---------------- CSR build ----------------
__global__ void k_init_cnt() {
    int i = blockIdx.x * blockDim.x + threadIdx.x;
    if (i < Nn) g_cnt[i] = 1;
}
__global__ void k_hist(const void* __restrict__ ei) {
    int i = blockIdx.x * blockDim.x + threadIdx.x;
    int is64 = g_is64;
    if (i < Ee) {
        int d = load_edge(ei, (long long)Ee + i, is64);
        atomicAdd(&g_cnt[d], 1);
    }
}
__global__ void k_scan1() {
    __shared__ int sm[SCAN_BS];
    int tid = threadIdx.x;
    int i = blockIdx.x * SCAN_BS + tid;
    int v = (i < Nn) ? g_cnt[i] : 0;
    sm[tid] = v;
    __syncthreads();
    #pragma unroll
    for (int off = 1; off < SCAN_BS; off <<= 1) {
        int t = (tid >= off) ? sm[tid - off] : 0;
        __syncthreads();
        sm[tid] += t;
        __syncthreads();
    }
    int incl = sm[tid];
    if (i < Nn) g_off[i] = incl - v;
    if (tid == SCAN_BS - 1) g_partials[blockIdx.x] = incl;
}
__global__ void k_scan2() {
    if (threadIdx.x == 0 && blockIdx.x == 0) {
        int run = 0;
        for (int b = 0; b < SCAN_NBLK; b++) {
            int t = g_partials[b];
            g_partials[b] = run;
            run += t;
        }
    }
}
__global__ void k_scan3() {
    int i = blockIdx.x * blockDim.x + threadIdx.x;
    if (i < Nn) {
        int o = g_off[i] + g_partials[i / SCAN_BS];
        g_off[i] = o;
        g_cursor[i] = o;
    }
    if (i == 0) g_off[Nn] = EN;
}
__global__ void k_scatter(const void* __restrict__ ei) {
    int i = blockIdx.x * blockDim.x + threadIdx.x;
    if (i >= EN) return;
    int is64 = g_is64;
    int s, d;
    if (i < Ee) {
        s = load_edge(ei, i, is64);
        d = load_edge(ei, (long long)Ee + i, is64);
    } else {
        s = d = i - Ee;
    }
    int pos = atomicAdd(&g_cursor[d], 1);
    if (pos >= 0 && pos < EN) g_csr_src[pos] = s;
}

// ---------------- W1 pre-convert + alpha zero-init ----------------
__global__ void k_convW(const float* __restrict__ W1) {
    int idx = blockIdx.x * blockDim.x + threadIdx.x;
    if (idx < 64 * 128) {   // n*128 + k4
        int n = idx >> 7, k4 = idx & 127;
        float f[4], lo[4];
        #pragma unroll
        for (int j = 0; j < 4; j++) {
            f[j] = W1[(size_t)(k4 * 4 + j) * FHID + n];
            __nv_bfloat16 hb = __float2bfloat16(f[j]);
            lo[j] = f[j] - __bfloat162float(hb);
        }
        g_wbh2[idx] = make_uint2(pack_bf2(f[0], f[1]), pack_bf2(f[2], f[3]));
        g_wbl2[idx] = make_uint2(pack_bf2(lo[0], lo[1]), pack_bf2(lo[2], lo[3]));
    }
    if (idx < Nn) { g_as1[idx] = 0.f; g_ad1[idx] = 0.f; }
}

// ---------------- GEMM1 via mma.sync bf16 hi/lo split, alpha1 fused ----------
#define ASTR 40   // 32 + 8 pad (bf16) -> 20-word row stride: conflict-free frags
__global__ __launch_bounds__(256) void k_gemm1_mma(const float* __restrict__ x,
                                                   const float* __restrict__ a_s,
                                                   const float* __restrict__ a_d) {
    __shared__ __nv_bfloat16 Ah[128][ASTR], Al[128][ASTR];
    __shared__ __nv_bfloat16 Bh[64][ASTR],  Bl[64][ASTR];
    int tid = threadIdx.x, wid = tid >> 5, lane = tid & 31;
    int warpM = wid & 3, warpN = wid >> 2;     // 4 x 2
    int rowBase = blockIdx.x * 128;
    int g = lane >> 2, tg = lane & 3;

    float acc[2][4][4];
    #pragma unroll
    for (int mt = 0; mt < 2; mt++)
        #pragma unroll
        for (int nt = 0; nt < 4; nt++)
            #pragma unroll
            for (int q = 0; q < 4; q++) acc[mt][nt][q] = 0.f;

    float4 aR[4];
    uint2  bhR[2], blR[2];

#define LOADR(c_) do { \
    _Pragma("unroll") for (int it = 0; it < 4; it++) { \
        int idx = tid + it * 256; int row = idx >> 3, kq = idx & 7; \
        int grow = rowBase + row; \
        aR[it] = (grow < Nn) ? *(const float4*)(x + (size_t)grow * FIN + (c_) * 32 + kq * 4) \
                             : make_float4(0.f, 0.f, 0.f, 0.f); \
    } \
    _Pragma("unroll") for (int it = 0; it < 2; it++) { \
        int idx = tid + it * 256; int n = idx >> 3, j = idx & 7; \
        bhR[it] = g_wbh2[n * 128 + (c_) * 8 + j]; \
        blR[it] = g_wbl2[n * 128 + (c_) * 8 + j]; \
    } } while (0)

#define STS() do { \
    _Pragma("unroll") for (int it = 0; it < 4; it++) { \
        int idx = tid + it * 256; int row = idx >> 3, kq = idx & 7; \
        float4 v = aR[it]; \
        uint32_t h01 = pack_bf2(v.x, v.y), h23 = pack_bf2(v.z, v.w); \
        __nv_bfloat162 hh01 = *reinterpret_cast<__nv_bfloat162*>(&h01); \
        __nv_bfloat162 hh23 = *reinterpret_cast<__nv_bfloat162*>(&h23); \
        uint32_t l01 = pack_bf2(v.x - __bfloat162float(hh01.x), v.y - __bfloat162float(hh01.y)); \
        uint32_t l23 = pack_bf2(v.z - __bfloat162float(hh23.x), v.w - __bfloat162float(hh23.y)); \
        *(uint2*)&Ah[row][kq * 4] = make_uint2(h01, h23); \
        *(uint2*)&Al[row][kq * 4] = make_uint2(l01, l23); \
    } \
    _Pragma("unroll") for (int it = 0; it < 2; it++) { \
        int idx = tid + it * 256; int n = idx >> 3, j = idx & 7; \
        *(uint2*)&Bh[n][j * 4] = bhR[it]; \
        *(uint2*)&Bl[n][j * 4] = blR[it]; \
    } } while (0)

    LOADR(0);
    STS();
    __syncthreads();

    for (int c = 0; c < 16; c++) {
        if (c < 15) LOADR(c + 1);          // prefetch overlaps compute
        #pragma unroll
        for (int kk = 0; kk < 2; kk++) {
            int kb = kk * 16;
            uint32_t aH[2][4], aL[2][4], bH[4][2], bL[4][2];
            #pragma unroll
            for (int mt = 0; mt < 2; mt++) {
                int r0 = warpM * 32 + mt * 16 + g;
                aH[mt][0] = *(const uint32_t*)&Ah[r0    ][kb + tg * 2];
                aH[mt][1] = *(const uint32_t*)&Ah[r0 + 8][kb + tg * 2];
                aH[mt][2] = *(const uint32_t*)&Ah[r0    ][kb + tg * 2 + 8];
                aH[mt][3] = *(const uint32_t*)&Ah[r0 + 8][kb + tg * 2 + 8];
                aL[mt][0] = *(const uint32_t*)&Al[r0    ][kb + tg * 2];
                aL[mt][1] = *(const uint32_t*)&Al[r0 + 8][kb + tg * 2];
                aL[mt][2] = *(const uint32_t*)&Al[r0    ][kb + tg * 2 + 8];
                aL[mt][3] = *(const uint32_t*)&Al[r0 + 8][kb + tg * 2 + 8];
            }
            #pragma unroll
            for (int nt = 0; nt < 4; nt++) {
                int n0 = warpN * 32 + nt * 8 + g;
                bH[nt][0] = *(const uint32_t*)&Bh[n0][kb + tg * 2];
                bH[nt][1] = *(const uint32_t*)&Bh[n0][kb + tg * 2 + 8];
                bL[nt][0] = *(const uint32_t*)&Bl[n0][kb + tg * 2];
                bL[nt][1] = *(const uint32_t*)&Bl[n0][kb + tg * 2 + 8];
            }
            #pragma unroll
            for (int mt = 0; mt < 2; mt++)
                #pragma unroll
                for (int nt = 0; nt < 4; nt++) {
                    MMA_BF16(acc[mt][nt], aH[mt], bH[nt]);
                    MMA_BF16(acc[mt][nt], aL[mt], bH[nt]);
                    MMA_BF16(acc[mt][nt], aH[mt], bL[nt]);
                }
        }
        __syncthreads();
        if (c < 15) {
            STS();
            __syncthreads();
        }
    }

    // epilogue: store h1 + fused alpha1 partial dots
    #pragma unroll
    for (int mt = 0; mt < 2; mt++) {
        int r = rowBase + warpM * 32 + mt * 16 + g;
        float ps0 = 0.f, pd0 = 0.f, ps1 = 0.f, pd1 = 0.f;
        #pragma unroll
        for (int nt = 0; nt < 4; nt++) {
            int cb = warpN * 32 + nt * 8 + tg * 2;
            if (r < Nn)
                *(float2*)(g_h1 + (size_t)r * FHID + cb) =
                    make_float2(acc[mt][nt][0], acc[mt][nt][1]);
            if (r + 8 < Nn)
                *(float2*)(g_h1 + (size_t)(r + 8) * FHID + cb) =
                    make_float2(acc[mt][nt][2], acc[mt][nt][3]);
            float a0s = __ldg(a_s + cb), a1s = __ldg(a_s + cb + 1);
            float a0d = __ldg(a_d + cb), a1d = __ldg(a_d + cb + 1);
            ps0 += acc[mt][nt][0] * a0s + acc[mt][nt][1] * a1s;
            pd0 += acc[mt][nt][0] * a0d + acc[mt][nt][1] * a1d;
            ps1 += acc[mt][nt][2] * a0s + acc[mt][nt][3] * a1s;
            pd1 += acc[mt][nt][2] * a0d + acc[mt][nt][3] * a1d;
        }
        #pragma unroll
        for (int o = 1; o <= 2; o <<= 1) {
            ps0 += __shfl_xor_sync(0xffffffffu, ps0, o);
            pd0 += __shfl_xor_sync(0xffffffffu, pd0, o);
            ps1 += __shfl_xor_sync(0xffffffffu, ps1, o);
            pd1 += __shfl_xor_sync(0xffffffffu, pd1, o);
        }
        if (tg == 0) {
            if (r < Nn)     { atomicAdd(&g_as1[r], ps0);     atomicAdd(&g_ad1[r], pd0); }
            if (r + 8 < Nn) { atomicAdd(&g_as1[r + 8], ps1); atomicAdd(&g_ad1[r + 8], pd1); }
        }
    }
#undef LOADR
#undef STS
}

// ------- fused: layer-1 aggregation (two-pass max) + relu + GEMM2 + alpha2 ---
// 32 warps/block (1024 thr), one node per warp; grid = Nn/32 = 3125 exact.
__global__ __launch_bounds__(1024) void k_agg1g2(const float* __restrict__ b1,
                                                 const float* __restrict__ W2,
                                                 const float* __restrict__ a_s2,
                                                 const float* __restrict__ a_d2) {
    __shared__ float W2s[FHID * FOUT];       // [k][c] 10 KB
    __shared__ float s_as[FOUT], s_ad[FOUT], b1s[FHID];
    __shared__ float ws[32][FHID];           // 8 KB
    int tid = threadIdx.x, wid = tid >> 5, lane = tid & 31;

    for (int t = tid; t < FHID * FOUT; t += 1024) W2s[t] = W2[t];
    if (tid < FOUT) { s_as[tid] = a_s2[tid]; s_ad[tid] = a_d2[tid]; }
    if (tid < FHID) b1s[tid] = b1[tid];
    __syncthreads();

    int d = blockIdx.x * 32 + wid;
    int beg = __ldg(&g_off[d]), end = __ldg(&g_off[d + 1]);
    float add = g_ad1[d];

    // pass 1: per-node max (lanes over edges; also warms csr/as1 caches)
    float m = -3.402823e38f;
    for (int e = beg + lane; e < end; e += 32) {
        int s = __ldg(&g_csr_src[e]);
        s = (unsigned)s >= Nn ? 0 : s;
        m = fmaxf(m, leaky(__ldg(&g_as1[s]) + add));
    }
    #pragma unroll
    for (int o = 16; o; o >>= 1) m = fmaxf(m, __shfl_xor_sync(0xffffffffu, m, o));

    // pass 2: serial over edges, lanes over features (2 feats/lane)
    float acc0 = 0.f, acc1 = 0.f, ssum = 0.f;
    for (int e = beg; e < end; ++e) {
        int s = __ldg(&g_csr_src[e]);
        s = (unsigned)s >= Nn ? 0 : s;
        float w = __expf(leaky(__ldg(&g_as1[s]) + add) - m);
        ssum += w;
        float2 hv = *(const float2*)(g_h1 + (size_t)s * FHID + 2 * lane);
        acc0 += w * hv.x;
        acc1 += w * hv.y;
    }
    float inv = 1.f / ssum;
    ws[wid][2 * lane]     = fmaxf(acc0 * inv + b1s[2 * lane], 0.f);
    ws[wid][2 * lane + 1] = fmaxf(acc1 * inv + b1s[2 * lane + 1], 0.f);
    __syncwarp();

    // matvec 64x40: lane computes output c=lane (and c=lane+32 when lane<8)
    const float* row = ws[wid];
    int c2 = lane + 32;
    float h0 = 0.f, h1v = 0.f;
    #pragma unroll
    for (int k = 0; k < FHID; k++) {
        float rv = row[k];
        h0 += rv * W2s[k * FOUT + lane];
        if (c2 < FOUT) h1v += rv * W2s[k * FOUT + c2];
    }
    float* orow = g_h2 + (size_t)d * FOUT;
    if (lane < FOUT) orow[lane] = h0;
    if (c2 < FOUT) orow[c2] = h1v;

    // alpha2 = h2 . a_src2 / a_dst2 (warp-reduce partials)
    float ps = (lane < FOUT) ? h0 * s_as[lane] : 0.f;
    float pd = (lane < FOUT) ? h0 * s_ad[lane] : 0.f;
    if (c2 < FOUT) { ps += h1v * s_as[c2]; pd += h1v * s_ad[c2]; }
    #pragma unroll
    for (int o = 16; o; o >>= 1) {
        ps += __shfl_xor_sync(0xffffffffu, ps, o);
        pd += __shfl_xor_sync(0xffffffffu, pd, o);
    }
    if (lane == 0) {
        g_as2[d] = ps;
        g_ad2[d] = pd;
    }
}

// ---------------- layer-2 aggregation + bias + log_softmax (two-pass) --------
__global__ __launch_bounds__(256) void k_agg2(const float* __restrict__ b2,
                                              float* __restrict__ out) {
    int warp = (blockIdx.x * blockDim.x + threadIdx.x) >> 5;
    int lane = threadIdx.x & 31;
    if (warp >= Nn) return;
    int d = warp;
    int beg = __ldg(&g_off[d]), end = __ldg(&g_off[d + 1]);
    float add = g_ad2[d];

    float m = -3.402823e38f;
    for (int e = beg + lane; e < end; e += 32) {
        int s = __ldg(&g_csr_src[e]);
        s = (unsigned)s >= Nn ? 0 : s;
        m = fmaxf(m, leaky(__ldg(&g_as2[s]) + add));
    }
    #pragma unroll
    for (int o = 16; o; o >>= 1) m = fmaxf(m, __shfl_xor_sync(0xffffffffu, m, o));

    float acc0 = 0.f, acc1 = 0.f, ssum = 0.f;
    for (int e = beg; e < end; ++e) {
        int s = __ldg(&g_csr_src[e]);
        s = (unsigned)s >= Nn ? 0 : s;
        float w = __expf(leaky(__ldg(&g_as2[s]) + add) - m);
        ssum += w;
        const float* hrow = g_h2 + (size_t)s * FOUT;
        acc0 += w * hrow[lane];
        if (lane < FOUT - 32) acc1 += w * hrow[32 + lane];
    }
    float inv = 1.f / ssum;
    float v0 = acc0 * inv + b2[lane];
    float v1 = (lane < FOUT - 32) ? acc1 * inv + b2[32 + lane] : -3.402823e38f;

    // log_softmax over the 40 values held by the warp
    float mx = fmaxf(v0, v1);
    #pragma unroll
    for (int o = 16; o; o >>= 1) mx = fmaxf(mx, __shfl_xor_sync(0xffffffffu, mx, o));
    float se = __expf(v0 - mx) + ((lane < FOUT - 32) ? __expf(v1 - mx) : 0.f);
    #pragma unroll
    for (int o = 16; o; o >>= 1) se += __shfl_xor_sync(0xffffffffu, se, o);
    float lse = logf(se);

    float* orow = out + (size_t)d * FOUT;
    orow[lane] = v0 - mx - lse;
    if (lane < FOUT - 32) orow[32 + lane] = v1 - mx - lse;
}

// ---------------- launcher ----------------
extern "C" void kernel_launch(void* const* d_in, const int* in_sizes, int n_in,
                              void* d_out, int out_size) {
    const float* x      = (const float*)d_in[0];
    const void*  ei     = d_in[1];
    const float* W1     = (const float*)d_in[2];
    const float* a_src1 = (const float*)d_in[3];
    const float* a_dst1 = (const float*)d_in[4];
    const float* b1     = (const float*)d_in[5];
    const float* W2     = (const float*)d_in[6];
    const float* a_src2 = (const float*)d_in[7];
    const float* a_dst2 = (const float*)d_in[8];
    const float* b2     = (const float*)d_in[9];
    float* out = (float*)d_out;

    // detect dtype on main stream, then fork CSR chain onto side stream
    k_detect<<<1, 256>>>((const int2*)ei);
    cudaEventRecord(g_evFork, 0);
    cudaStreamWaitEvent(g_s2, g_evFork, 0);

    // side stream: CSR build (independent of GEMM1)
    k_init_cnt<<<(Nn + 255) / 256, 256, 0, g_s2>>>();
    k_hist<<<(Ee + 255) / 256, 256, 0, g_s2>>>(ei);
    k_scan1<<<SCAN_NBLK, SCAN_BS, 0, g_s2>>>();
    k_scan2<<<1, 32, 0, g_s2>>>();
    k_scan3<<<(Nn + 255) / 256, 256, 0, g_s2>>>();
    k_scatter<<<(EN + 255) / 256, 256, 0, g_s2>>>(ei);
    cudaEventRecord(g_evJoin, g_s2);

    // main stream: W1 convert + init, then GEMM1 with fused alpha1
    k_convW<<<(Nn + 255) / 256, 256>>>(W1);
    k_gemm1_mma<<<TILES, 256>>>(x, a_src1, a_dst1);

    // join: fused agg1+gemm2 needs CSR + gemm1 results
    cudaStreamWaitEvent(0, g_evJoin, 0);
    k_agg1g2<<<Nn / 32, 1024>>>(b1, W2, a_src2, a_dst2);

    // layer-2 aggregation + log_softmax
    k_agg2<<<(Nn * 32 + 255) / 256, 256>>>(b2, out);
}

// round 9
// speedup vs baseline: 1.1546x; 1.1546x over previous
#include <cuda_runtime.h>
#include <cuda_bf16.h>
#include <math.h>
#include <stdint.h>

// ---------------- problem constants ----------------
#define Nn   100000
#define Ee   1600000
#define EN   (Ee + Nn)          // edges incl. self loops = 1,700,000
#define FIN  512
#define FHID 64
#define FOUT 40
#define NEG_SLOPE 0.2f
#define TILES ((Nn + 127) / 128)   // 782

// ---------------- device scratch (no dynamic alloc allowed) ----------------
__device__ __align__(16) float g_h1 [(size_t)Nn * FHID];   // x@W1
__device__ __align__(16) float g_h1r[(size_t)Nn * FHID];   // relu(layer1 out)
__device__ __align__(16) float g_h2 [(size_t)Nn * FOUT];   // h1r@W2
__device__ float g_as1[Nn], g_ad1[Nn];
__device__ float g_as2[Nn], g_ad2[Nn];
__device__ int   g_cnt[Nn];
__device__ int   g_off[Nn + 1];
__device__ int   g_cursor[Nn];
__device__ int   g_csr_src[EN];
__device__ int   g_is64;
// W1 pre-converted: [n][k] K-contiguous bf16 hi/lo, stored as uint2 = 4 bf16 along k
__device__ __align__(16) uint2 g_wbh2[64 * 128];
__device__ __align__(16) uint2 g_wbl2[64 * 128];

#define SCAN_BS   1024
#define SCAN_NBLK ((Nn + SCAN_BS - 1) / SCAN_BS)   // 98
__device__ int g_partials[SCAN_NBLK];

__device__ __forceinline__ uint32_t pack_bf2(float a, float b) {
    __nv_bfloat162 t = __floats2bfloat162_rn(a, b);
    return *reinterpret_cast<uint32_t*>(&t);
}
__device__ __forceinline__ float leaky(float z) { return z > 0.f ? z : NEG_SLOPE * z; }

// mma.sync m16n8k16 row.col f32.bf16.bf16.f32 (sm_80+ PTX, valid on sm_100)
#define MMA_BF16(c, a, b) \
    asm volatile("mma.sync.aligned.m16n8k16.row.col.f32.bf16.bf16.f32 " \
        "{%0,%1,%2,%3}, {%4,%5,%6,%7}, {%8,%9}, {%0,%1,%2,%3};" \
        : "+f"((c)[0]), "+f"((c)[1]), "+f"((c)[2]), "+f"((c)[3]) \
        : "r"((a)[0]), "r"((a)[1]), "r"((a)[2]), "r"((a)[3]), "r"((b)[0]), "r"((b)[1]))

// ---------------- streams for fork-join overlap (created once, pre-main) ----
static cudaStream_t g_s2;
static cudaEvent_t  g_evFork, g_evJoin;
static struct _StreamInit {
    _StreamInit() {
        cudaStreamCreateWithFlags(&g_s2, cudaStreamNonBlocking);
        cudaEventCreateWithFlags(&g_evFork, cudaEventDisableTiming);
        cudaEventCreateWithFlags(&g_evJoin, cudaEventDisableTiming);
    }
} g_streamInit;

// ---------------- dtype detection ----------------
__global__ void k_detect(const int2* __restrict__ p) {
    __shared__ int flag;
    if (threadIdx.x == 0) flag = 0;
    __syncthreads();
    int nz = 0;
    for (int i = threadIdx.x; i < 1024; i += blockDim.x)
        if (p[i].y != 0) nz = 1;
    if (nz) atomicOr(&flag, 1);
    __syncthreads();
    if (threadIdx.x == 0) g_is64 = (flag == 0) ? 1 : 0;
}

__device__ __forceinline__ int load_edge(const void* ei, long long idx, int is64) {
    int v;
    if (is64) v = (int)((const long long*)ei)[idx];
    else      v = ((const int*)ei)[idx];
    v = v < 0 ? 0 : (v >= Nn ? Nn - 1 : v);
    return v;
}

// ---------------- CSR build ----------------
__global__ void k_init_cnt() {
    int i = blockIdx.x * blockDim.x + threadIdx.x;
    if (i < Nn) g_cnt[i] = 1;
}
__global__ void k_hist(const void* __restrict__ ei) {
    int i = blockIdx.x * blockDim.x + threadIdx.x;
    int is64 = g_is64;
    if (i < Ee) {
        int d = load_edge(ei, (long long)Ee + i, is64);
        atomicAdd(&g_cnt[d], 1);
    }
}
__global__ void k_scan1() {
    __shared__ int sm[SCAN_BS];
    int tid = threadIdx.x;
    int i = blockIdx.x * SCAN_BS + tid;
    int v = (i < Nn) ? g_cnt[i] : 0;
    sm[tid] = v;
    __syncthreads();
    #pragma unroll
    for (int off = 1; off < SCAN_BS; off <<= 1) {
        int t = (tid >= off) ? sm[tid - off] : 0;
        __syncthreads();
        sm[tid] += t;
        __syncthreads();
    }
    int incl = sm[tid];
    if (i < Nn) g_off[i] = incl - v;
    if (tid == SCAN_BS - 1) g_partials[blockIdx.x] = incl;
}
__global__ void k_scan2() {
    if (threadIdx.x == 0 && blockIdx.x == 0) {
        int run = 0;
        for (int b = 0; b < SCAN_NBLK; b++) {
            int t = g_partials[b];
            g_partials[b] = run;
            run += t;
        }
    }
}
__global__ void k_scan3() {
    int i = blockIdx.x * blockDim.x + threadIdx.x;
    if (i < Nn) {
        int o = g_off[i] + g_partials[i / SCAN_BS];
        g_off[i] = o;
        g_cursor[i] = o;
    }
    if (i == 0) g_off[Nn] = EN;
}
__global__ void k_scatter(const void* __restrict__ ei) {
    int i = blockIdx.x * blockDim.x + threadIdx.x;
    if (i >= EN) return;
    int is64 = g_is64;
    int s, d;
    if (i < Ee) {
        s = load_edge(ei, i, is64);
        d = load_edge(ei, (long long)Ee + i, is64);
    } else {
        s = d = i - Ee;
    }
    int pos = atomicAdd(&g_cursor[d], 1);
    if (pos >= 0 && pos < EN) g_csr_src[pos] = s;
}

// ---------------- W1 pre-convert + alpha zero-init ----------------
__global__ void k_convW(const float* __restrict__ W1) {
    int idx = blockIdx.x * blockDim.x + threadIdx.x;
    if (idx < 64 * 128) {   // n*128 + k4
        int n = idx >> 7, k4 = idx & 127;
        float f[4], lo[4];
        #pragma unroll
        for (int j = 0; j < 4; j++) {
            f[j] = W1[(size_t)(k4 * 4 + j) * FHID + n];
            __nv_bfloat16 hb = __float2bfloat16(f[j]);
            lo[j] = f[j] - __bfloat162float(hb);
        }
        g_wbh2[idx] = make_uint2(pack_bf2(f[0], f[1]), pack_bf2(f[2], f[3]));
        g_wbl2[idx] = make_uint2(pack_bf2(lo[0], lo[1]), pack_bf2(lo[2], lo[3]));
    }
    if (idx < Nn) { g_as1[idx] = 0.f; g_ad1[idx] = 0.f; }
}

// ---------------- GEMM1 via mma.sync bf16 hi/lo split, alpha1 fused ----------
#define ASTR 40   // 32 + 8 pad (bf16) -> 20-word row stride: conflict-free frags
__global__ __launch_bounds__(256) void k_gemm1_mma(const float* __restrict__ x,
                                                   const float* __restrict__ a_s,
                                                   const float* __restrict__ a_d) {
    __shared__ __nv_bfloat16 Ah[128][ASTR], Al[128][ASTR];
    __shared__ __nv_bfloat16 Bh[64][ASTR],  Bl[64][ASTR];
    int tid = threadIdx.x, wid = tid >> 5, lane = tid & 31;
    int warpM = wid & 3, warpN = wid >> 2;     // 4 x 2
    int rowBase = blockIdx.x * 128;
    int g = lane >> 2, tg = lane & 3;

    float acc[2][4][4];
    #pragma unroll
    for (int mt = 0; mt < 2; mt++)
        #pragma unroll
        for (int nt = 0; nt < 4; nt++)
            #pragma unroll
            for (int q = 0; q < 4; q++) acc[mt][nt][q] = 0.f;

    float4 aR[4];
    uint2  bhR[2], blR[2];

#define LOADR(c_) do { \
    _Pragma("unroll") for (int it = 0; it < 4; it++) { \
        int idx = tid + it * 256; int row = idx >> 3, kq = idx & 7; \
        int grow = rowBase + row; \
        aR[it] = (grow < Nn) ? *(const float4*)(x + (size_t)grow * FIN + (c_) * 32 + kq * 4) \
                             : make_float4(0.f, 0.f, 0.f, 0.f); \
    } \
    _Pragma("unroll") for (int it = 0; it < 2; it++) { \
        int idx = tid + it * 256; int n = idx >> 3, j = idx & 7; \
        bhR[it] = g_wbh2[n * 128 + (c_) * 8 + j]; \
        blR[it] = g_wbl2[n * 128 + (c_) * 8 + j]; \
    } } while (0)

#define STS() do { \
    _Pragma("unroll") for (int it = 0; it < 4; it++) { \
        int idx = tid + it * 256; int row = idx >> 3, kq = idx & 7; \
        float4 v = aR[it]; \
        uint32_t h01 = pack_bf2(v.x, v.y), h23 = pack_bf2(v.z, v.w); \
        __nv_bfloat162 hh01 = *reinterpret_cast<__nv_bfloat162*>(&h01); \
        __nv_bfloat162 hh23 = *reinterpret_cast<__nv_bfloat162*>(&h23); \
        uint32_t l01 = pack_bf2(v.x - __bfloat162float(hh01.x), v.y - __bfloat162float(hh01.y)); \
        uint32_t l23 = pack_bf2(v.z - __bfloat162float(hh23.x), v.w - __bfloat162float(hh23.y)); \
        *(uint2*)&Ah[row][kq * 4] = make_uint2(h01, h23); \
        *(uint2*)&Al[row][kq * 4] = make_uint2(l01, l23); \
    } \
    _Pragma("unroll") for (int it = 0; it < 2; it++) { \
        int idx = tid + it * 256; int n = idx >> 3, j = idx & 7; \
        *(uint2*)&Bh[n][j * 4] = bhR[it]; \
        *(uint2*)&Bl[n][j * 4] = blR[it]; \
    } } while (0)

    LOADR(0);
    STS();
    __syncthreads();

    for (int c = 0; c < 16; c++) {
        if (c < 15) LOADR(c + 1);          // prefetch overlaps compute
        #pragma unroll
        for (int kk = 0; kk < 2; kk++) {
            int kb = kk * 16;
            uint32_t aH[2][4], aL[2][4], bH[4][2], bL[4][2];
            #pragma unroll
            for (int mt = 0; mt < 2; mt++) {
                int r0 = warpM * 32 + mt * 16 + g;
                aH[mt][0] = *(const uint32_t*)&Ah[r0    ][kb + tg * 2];
                aH[mt][1] = *(const uint32_t*)&Ah[r0 + 8][kb + tg * 2];
                aH[mt][2] = *(const uint32_t*)&Ah[r0    ][kb + tg * 2 + 8];
                aH[mt][3] = *(const uint32_t*)&Ah[r0 + 8][kb + tg * 2 + 8];
                aL[mt][0] = *(const uint32_t*)&Al[r0    ][kb + tg * 2];
                aL[mt][1] = *(const uint32_t*)&Al[r0 + 8][kb + tg * 2];
                aL[mt][2] = *(const uint32_t*)&Al[r0    ][kb + tg * 2 + 8];
                aL[mt][3] = *(const uint32_t*)&Al[r0 + 8][kb + tg * 2 + 8];
            }
            #pragma unroll
            for (int nt = 0; nt < 4; nt++) {
                int n0 = warpN * 32 + nt * 8 + g;
                bH[nt][0] = *(const uint32_t*)&Bh[n0][kb + tg * 2];
                bH[nt][1] = *(const uint32_t*)&Bh[n0][kb + tg * 2 + 8];
                bL[nt][0] = *(const uint32_t*)&Bl[n0][kb + tg * 2];
                bL[nt][1] = *(const uint32_t*)&Bl[n0][kb + tg * 2 + 8];
            }
            #pragma unroll
            for (int mt = 0; mt < 2; mt++)
                #pragma unroll
                for (int nt = 0; nt < 4; nt++) {
                    MMA_BF16(acc[mt][nt], aH[mt], bH[nt]);
                    MMA_BF16(acc[mt][nt], aL[mt], bH[nt]);
                    MMA_BF16(acc[mt][nt], aH[mt], bL[nt]);
                }
        }
        __syncthreads();
        if (c < 15) {
            STS();
            __syncthreads();
        }
    }

    // epilogue: store h1 + fused alpha1 partial dots
    #pragma unroll
    for (int mt = 0; mt < 2; mt++) {
        int r = rowBase + warpM * 32 + mt * 16 + g;
        float ps0 = 0.f, pd0 = 0.f, ps1 = 0.f, pd1 = 0.f;
        #pragma unroll
        for (int nt = 0; nt < 4; nt++) {
            int cb = warpN * 32 + nt * 8 + tg * 2;
            if (r < Nn)
                *(float2*)(g_h1 + (size_t)r * FHID + cb) =
                    make_float2(acc[mt][nt][0], acc[mt][nt][1]);
            if (r + 8 < Nn)
                *(float2*)(g_h1 + (size_t)(r + 8) * FHID + cb) =
                    make_float2(acc[mt][nt][2], acc[mt][nt][3]);
            float a0s = __ldg(a_s + cb), a1s = __ldg(a_s + cb + 1);
            float a0d = __ldg(a_d + cb), a1d = __ldg(a_d + cb + 1);
            ps0 += acc[mt][nt][0] * a0s + acc[mt][nt][1] * a1s;
            pd0 += acc[mt][nt][0] * a0d + acc[mt][nt][1] * a1d;
            ps1 += acc[mt][nt][2] * a0s + acc[mt][nt][3] * a1s;
            pd1 += acc[mt][nt][2] * a0d + acc[mt][nt][3] * a1d;
        }
        #pragma unroll
        for (int o = 1; o <= 2; o <<= 1) {
            ps0 += __shfl_xor_sync(0xffffffffu, ps0, o);
            pd0 += __shfl_xor_sync(0xffffffffu, pd0, o);
            ps1 += __shfl_xor_sync(0xffffffffu, ps1, o);
            pd1 += __shfl_xor_sync(0xffffffffu, pd1, o);
        }
        if (tg == 0) {
            if (r < Nn)     { atomicAdd(&g_as1[r], ps0);     atomicAdd(&g_ad1[r], pd0); }
            if (r + 8 < Nn) { atomicAdd(&g_as1[r + 8], ps1); atomicAdd(&g_ad1[r + 8], pd1); }
        }
    }
#undef LOADR
#undef STS
}

// ---------------- layer-1 aggregation: warp per node, batched edges ----------
__global__ __launch_bounds__(256) void k_agg1(const float* __restrict__ b1) {
    int warp = (blockIdx.x * blockDim.x + threadIdx.x) >> 5;
    int lane = threadIdx.x & 31;
    if (warp >= Nn) return;
    int d = warp;
    int beg = __ldg(&g_off[d]), end = __ldg(&g_off[d + 1]);
    float add = g_ad1[d];

    // pass 1: per-node max (lanes over edges; also warms csr/as1 caches)
    float m = -3.402823e38f;
    for (int e = beg + lane; e < end; e += 32) {
        int s = __ldg(&g_csr_src[e]);
        s = (unsigned)s >= Nn ? 0 : s;
        m = fmaxf(m, __ldg(&g_as1[s]));
    }
    #pragma unroll
    for (int o = 16; o; o >>= 1) m = fmaxf(m, __shfl_xor_sync(0xffffffffu, m, o));
    m = leaky(m + add);   // leaky monotone: max of leaky = leaky of max

    // pass 2: 32-edge tiles; lane computes its edge's (s,w), then all lanes
    // stream h1 rows with shuffled (s,w) -> high MLP, coalesced 256B rows
    float acc0 = 0.f, acc1 = 0.f, ssum = 0.f;
    for (int base = beg; base < end; base += 32) {
        int e = base + lane;
        int s_l = 0;
        float w_l = 0.f;
        if (e < end) {
            s_l = __ldg(&g_csr_src[e]);
            s_l = (unsigned)s_l >= Nn ? 0 : s_l;
            w_l = __expf(leaky(__ldg(&g_as1[s_l]) + add) - m);
        }
        ssum += w_l;
        int cnt = min(32, end - base);
        #pragma unroll 4
        for (int j = 0; j < cnt; j++) {
            int   s = __shfl_sync(0xffffffffu, s_l, j);
            float w = __shfl_sync(0xffffffffu, w_l, j);
            float2 hv = *(const float2*)(g_h1 + (size_t)s * FHID + 2 * lane);
            acc0 += w * hv.x;
            acc1 += w * hv.y;
        }
    }
    #pragma unroll
    for (int o = 16; o; o >>= 1) ssum += __shfl_xor_sync(0xffffffffu, ssum, o);

    float inv = 1.f / ssum;
    float v0 = fmaxf(acc0 * inv + b1[2 * lane], 0.f);
    float v1 = fmaxf(acc1 * inv + b1[2 * lane + 1], 0.f);
    *(float2*)(g_h1r + (size_t)d * FHID + 2 * lane) = make_float2(v0, v1);
}

// ---------------- GEMM2 + alpha2 fused ----------------
__global__ __launch_bounds__(128) void k_gemm2(const float* __restrict__ W2,
                                               const float* __restrict__ a_s,
                                               const float* __restrict__ a_d) {
    __shared__ float Ws[FHID * FOUT];
    __shared__ float s_as[FOUT], s_ad[FOUT];
    for (int t = threadIdx.x; t < FHID * FOUT; t += blockDim.x) Ws[t] = W2[t];
    if (threadIdx.x < FOUT) {
        s_as[threadIdx.x] = a_s[threadIdx.x];
        s_ad[threadIdx.x] = a_d[threadIdx.x];
    }
    __syncthreads();
    int i = blockIdx.x * blockDim.x + threadIdx.x;
    if (i >= Nn) return;
    float acc[FOUT];
    #pragma unroll
    for (int c = 0; c < FOUT; c++) acc[c] = 0.f;
    const float4* hr = (const float4*)(g_h1r + (size_t)i * FHID);
    #pragma unroll
    for (int k4 = 0; k4 < FHID / 4; k4++) {
        float4 xv = hr[k4];
        const float* w0 = &Ws[(k4 * 4 + 0) * FOUT];
        const float* w1 = &Ws[(k4 * 4 + 1) * FOUT];
        const float* w2 = &Ws[(k4 * 4 + 2) * FOUT];
        const float* w3 = &Ws[(k4 * 4 + 3) * FOUT];
        #pragma unroll
        for (int c = 0; c < FOUT; c++)
            acc[c] += xv.x * w0[c] + xv.y * w1[c] + xv.z * w2[c] + xv.w * w3[c];
    }
    float s = 0.f, dd = 0.f;
    #pragma unroll
    for (int c = 0; c < FOUT; c++) { s += acc[c] * s_as[c]; dd += acc[c] * s_ad[c]; }
    float* orow = g_h2 + (size_t)i * FOUT;
    #pragma unroll
    for (int c = 0; c < FOUT; c += 4)
        *(float4*)(orow + c) = make_float4(acc[c], acc[c + 1], acc[c + 2], acc[c + 3]);
    g_as2[i] = s;
    g_ad2[i] = dd;
}

// ---------------- layer-2 aggregation + bias + log_softmax -------------------
__global__ __launch_bounds__(256) void k_agg2(const float* __restrict__ b2,
                                              float* __restrict__ out) {
    int warp = (blockIdx.x * blockDim.x + threadIdx.x) >> 5;
    int lane = threadIdx.x & 31;
    if (warp >= Nn) return;
    int d = warp;
    int beg = __ldg(&g_off[d]), end = __ldg(&g_off[d + 1]);
    float add = g_ad2[d];

    float m = -3.402823e38f;
    for (int e = beg + lane; e < end; e += 32) {
        int s = __ldg(&g_csr_src[e]);
        s = (unsigned)s >= Nn ? 0 : s;
        m = fmaxf(m, __ldg(&g_as2[s]));
    }
    #pragma unroll
    for (int o = 16; o; o >>= 1) m = fmaxf(m, __shfl_xor_sync(0xffffffffu, m, o));
    m = leaky(m + add);

    float acc0 = 0.f, acc1 = 0.f, ssum = 0.f;
    for (int base = beg; base < end; base += 32) {
        int e = base + lane;
        int s_l = 0;
        float w_l = 0.f;
        if (e < end) {
            s_l = __ldg(&g_csr_src[e]);
            s_l = (unsigned)s_l >= Nn ? 0 : s_l;
            w_l = __expf(leaky(__ldg(&g_as2[s_l]) + add) - m);
        }
        ssum += w_l;
        int cnt = min(32, end - base);
        #pragma unroll 4
        for (int j = 0; j < cnt; j++) {
            int   s = __shfl_sync(0xffffffffu, s_l, j);
            float w = __shfl_sync(0xffffffffu, w_l, j);
            const float* hrow = g_h2 + (size_t)s * FOUT;
            acc0 += w * hrow[lane];
            if (lane < FOUT - 32) acc1 += w * hrow[32 + lane];
        }
    }
    #pragma unroll
    for (int o = 16; o; o >>= 1) ssum += __shfl_xor_sync(0xffffffffu, ssum, o);

    float inv = 1.f / ssum;
    float v0 = acc0 * inv + b2[lane];
    float v1 = (lane < FOUT - 32) ? acc1 * inv + b2[32 + lane] : -3.402823e38f;

    // log_softmax over the 40 values held by the warp
    float mx = fmaxf(v0, v1);
    #pragma unroll
    for (int o = 16; o; o >>= 1) mx = fmaxf(mx, __shfl_xor_sync(0xffffffffu, mx, o));
    float se = __expf(v0 - mx) + ((lane < FOUT - 32) ? __expf(v1 - mx) : 0.f);
    #pragma unroll
    for (int o = 16; o; o >>= 1) se += __shfl_xor_sync(0xffffffffu, se, o);
    float lse = logf(se);

    float* orow = out + (size_t)d * FOUT;
    orow[lane] = v0 - mx - lse;
    if (lane < FOUT - 32) orow[32 + lane] = v1 - mx - lse;
}

// ---------------- launcher ----------------
extern "C" void kernel_launch(void* const* d_in, const int* in_sizes, int n_in,
                              void* d_out, int out_size) {
    const float* x      = (const float*)d_in[0];
    const void*  ei     = d_in[1];
    const float* W1     = (const float*)d_in[2];
    const float* a_src1 = (const float*)d_in[3];
    const float* a_dst1 = (const float*)d_in[4];
    const float* b1     = (const float*)d_in[5];
    const float* W2     = (const float*)d_in[6];
    const float* a_src2 = (const float*)d_in[7];
    const float* a_dst2 = (const float*)d_in[8];
    const float* b2     = (const float*)d_in[9];
    float* out = (float*)d_out;

    // detect dtype on main stream, then fork CSR chain onto side stream
    k_detect<<<1, 256>>>((const int2*)ei);
    cudaEventRecord(g_evFork, 0);
    cudaStreamWaitEvent(g_s2, g_evFork, 0);

    // side stream: CSR build (independent of GEMM1)
    k_init_cnt<<<(Nn + 255) / 256, 256, 0, g_s2>>>();
    k_hist<<<(Ee + 255) / 256, 256, 0, g_s2>>>(ei);
    k_scan1<<<SCAN_NBLK, SCAN_BS, 0, g_s2>>>();
    k_scan2<<<1, 32, 0, g_s2>>>();
    k_scan3<<<(Nn + 255) / 256, 256, 0, g_s2>>>();
    k_scatter<<<(EN + 255) / 256, 256, 0, g_s2>>>(ei);
    cudaEventRecord(g_evJoin, g_s2);

    // main stream: W1 convert + init, then GEMM1 with fused alpha1
    k_convW<<<(Nn + 255) / 256, 256>>>(W1);
    k_gemm1_mma<<<TILES, 256>>>(x, a_src1, a_dst1);

    // join: agg1 needs CSR + gemm1 results
    cudaStreamWaitEvent(0, g_evJoin, 0);
    k_agg1<<<(Nn * 32 + 255) / 256, 256>>>(b1);

    // layer 2
    k_gemm2<<<(Nn + 127) / 128, 128>>>(W2, a_src2, a_dst2);
    k_agg2<<<(Nn * 32 + 255) / 256, 256>>>(b2, out);
}

// round 12
// speedup vs baseline: 1.1892x; 1.0299x over previous
#include <cuda_runtime.h>
#include <cuda_bf16.h>
#include <math.h>
#include <stdint.h>

// ---------------- problem constants ----------------
#define Nn   100000
#define Ee   1600000
#define EN   (Ee + Nn)          // edges incl. self loops = 1,700,000
#define FIN  512
#define FHID 64
#define FOUT 40
#define NEG_SLOPE 0.2f
#define TILES ((Nn + 127) / 128)   // 782

// ---------------- device scratch (no dynamic alloc allowed) ----------------
__device__ __align__(16) float g_h1 [(size_t)Nn * FHID];   // x@W1
__device__ __align__(16) float g_h1r[(size_t)Nn * FHID];   // relu(layer1 out)
__device__ __align__(16) float g_h2 [(size_t)Nn * FOUT];   // h1r@W2
__device__ float g_as1[Nn], g_ad1[Nn];
__device__ float g_as2[Nn], g_ad2[Nn];
__device__ int   g_cnt[Nn];
__device__ int   g_off[Nn + 1];
__device__ int   g_cursor[Nn];
__device__ int   g_csr_src[EN];
__device__ int   g_is64;
// W1 pre-converted: [n][k] K-contiguous bf16 hi/lo, stored as uint2 = 4 bf16 along k
__device__ __align__(16) uint2 g_wbh2[64 * 128];
__device__ __align__(16) uint2 g_wbl2[64 * 128];

#define SCAN_BS   1024
#define SCAN_NBLK ((Nn + SCAN_BS - 1) / SCAN_BS)   // 98
__device__ int g_partials[SCAN_NBLK];

__device__ __forceinline__ uint32_t pack_bf2(float a, float b) {
    __nv_bfloat162 t = __floats2bfloat162_rn(a, b);
    return *reinterpret_cast<uint32_t*>(&t);
}
__device__ __forceinline__ float leaky(float z) { return z > 0.f ? z : NEG_SLOPE * z; }

// mma.sync m16n8k16 row.col f32.bf16.bf16.f32 (sm_80+ PTX, valid on sm_100)
#define MMA_BF16(c, a, b) \
    asm volatile("mma.sync.aligned.m16n8k16.row.col.f32.bf16.bf16.f32 " \
        "{%0,%1,%2,%3}, {%4,%5,%6,%7}, {%8,%9}, {%0,%1,%2,%3};" \
        : "+f"((c)[0]), "+f"((c)[1]), "+f"((c)[2]), "+f"((c)[3]) \
        : "r"((a)[0]), "r"((a)[1]), "r"((a)[2]), "r"((a)[3]), "r"((b)[0]), "r"((b)[1]))

// ---------------- GEMM1 smem sizing (needed by initializer below) ------------
#define ASTR 40                           // 32 + 8 pad bf16
#define ABY  (128 * ASTR * 2)             // 10240 B per A buffer
#define BBY  (64 * ASTR * 2)              // 5120 B per B buffer
#define STAGEB (2 * ABY + 2 * BBY)        // 30720 B per stage
#define SMTOT  (2 * STAGEB)               // 61440 B dynamic smem

__global__ __launch_bounds__(256) void k_gemm1_mma(const float* __restrict__ x,
                                                   const float* __restrict__ a_s,
                                                   const float* __restrict__ a_d);

// ---------------- streams + one-time func config (pre-main) ----------------
static cudaStream_t g_s2;
static cudaEvent_t  g_evFork, g_evJoin;
static struct _StreamInit {
    _StreamInit() {
        cudaStreamCreateWithFlags(&g_s2, cudaStreamNonBlocking);
        cudaEventCreateWithFlags(&g_evFork, cudaEventDisableTiming);
        cudaEventCreateWithFlags(&g_evJoin, cudaEventDisableTiming);
        cudaFuncSetAttribute(k_gemm1_mma,
                             cudaFuncAttributeMaxDynamicSharedMemorySize, SMTOT);
    }
} g_streamInit;

// ---------------- dtype detection ----------------
__global__ void k_detect(const int2* __restrict__ p) {
    __shared__ int flag;
    if (threadIdx.x == 0) flag = 0;
    __syncthreads();
    int nz = 0;
    for (int i = threadIdx.x; i < 1024; i += blockDim.x)
        if (p[i].y != 0) nz = 1;
    if (nz) atomicOr(&flag, 1);
    __syncthreads();
    if (threadIdx.x == 0) g_is64 = (flag == 0) ? 1 : 0;
}

__device__ __forceinline__ int load_edge(const void* ei, long long idx, int is64) {
    int v;
    if (is64) v = (int)((const long long*)ei)[idx];
    else      v = ((const int*)ei)[idx];
    v = v < 0 ? 0 : (v >= Nn ? Nn - 1 : v);
    return v;
}

// ---------------- CSR build ----------------
__global__ void k_init_cnt() {
    int i = blockIdx.x * blockDim.x + threadIdx.x;
    if (i < Nn) g_cnt[i] = 1;
}
__global__ void k_hist(const void* __restrict__ ei) {
    int i = blockIdx.x * blockDim.x + threadIdx.x;
    int is64 = g_is64;
    if (i < Ee) {
        int d = load_edge(ei, (long long)Ee + i, is64);
        atomicAdd(&g_cnt[d], 1);
    }
}
__global__ void k_scan1() {
    __shared__ int sm[SCAN_BS];
    int tid = threadIdx.x;
    int i = blockIdx.x * SCAN_BS + tid;
    int v = (i < Nn) ? g_cnt[i] : 0;
    sm[tid] = v;
    __syncthreads();
    #pragma unroll
    for (int off = 1; off < SCAN_BS; off <<= 1) {
        int t = (tid >= off) ? sm[tid - off] : 0;
        __syncthreads();
        sm[tid] += t;
        __syncthreads();
    }
    int incl = sm[tid];
    if (i < Nn) g_off[i] = incl - v;
    if (tid == SCAN_BS - 1) g_partials[blockIdx.x] = incl;
}
__global__ void k_scan2() {
    if (threadIdx.x == 0 && blockIdx.x == 0) {
        int run = 0;
        for (int b = 0; b < SCAN_NBLK; b++) {
            int t = g_partials[b];
            g_partials[b] = run;
            run += t;
        }
    }
}
__global__ void k_scan3() {
    int i = blockIdx.x * blockDim.x + threadIdx.x;
    if (i < Nn) {
        int o = g_off[i] + g_partials[i / SCAN_BS];
        g_off[i] = o;
        g_cursor[i] = o;
    }
    if (i == 0) g_off[Nn] = EN;
}
__global__ void k_scatter(const void* __restrict__ ei) {
    int i = blockIdx.x * blockDim.x + threadIdx.x;
    if (i >= EN) return;
    int is64 = g_is64;
    int s, d;
    if (i < Ee) {
        s = load_edge(ei, i, is64);
        d = load_edge(ei, (long long)Ee + i, is64);
    } else {
        s = d = i - Ee;
    }
    int pos = atomicAdd(&g_cursor[d], 1);
    if (pos >= 0 && pos < EN) g_csr_src[pos] = s;
}

// ---------------- W1 pre-convert + alpha zero-init ----------------
__global__ void k_convW(const float* __restrict__ W1) {
    int idx = blockIdx.x * blockDim.x + threadIdx.x;
    if (idx < 64 * 128) {   // n*128 + k4
        int n = idx >> 7, k4 = idx & 127;
        float f[4], lo[4];
        #pragma unroll
        for (int j = 0; j < 4; j++) {
            f[j] = W1[(size_t)(k4 * 4 + j) * FHID + n];
            __nv_bfloat16 hb = __float2bfloat16(f[j]);
            lo[j] = f[j] - __bfloat162float(hb);
        }
        g_wbh2[idx] = make_uint2(pack_bf2(f[0], f[1]), pack_bf2(f[2], f[3]));
        g_wbl2[idx] = make_uint2(pack_bf2(lo[0], lo[1]), pack_bf2(lo[2], lo[3]));
    }
    if (idx < Nn) { g_as1[idx] = 0.f; g_ad1[idx] = 0.f; }
}

// ---------------- GEMM1 via mma.sync bf16 hi/lo split, double-buffered -------
__global__ __launch_bounds__(256) void k_gemm1_mma(const float* __restrict__ x,
                                                   const float* __restrict__ a_s,
                                                   const float* __restrict__ a_d) {
    extern __shared__ char dynsm[];
    int tid = threadIdx.x, wid = tid >> 5, lane = tid & 31;
    int warpM = wid & 3, warpN = wid >> 2;     // 4 x 2
    int rowBase = blockIdx.x * 128;
    int g = lane >> 2, tg = lane & 3;

#define PAH(s) ((__nv_bfloat16(*)[ASTR])(dynsm + (s) * STAGEB))
#define PAL(s) ((__nv_bfloat16(*)[ASTR])(dynsm + (s) * STAGEB + ABY))
#define PBH(s) ((__nv_bfloat16(*)[ASTR])(dynsm + (s) * STAGEB + 2 * ABY))
#define PBL(s) ((__nv_bfloat16(*)[ASTR])(dynsm + (s) * STAGEB + 2 * ABY + BBY))

    float acc[2][4][4];
    #pragma unroll
    for (int mt = 0; mt < 2; mt++)
        #pragma unroll
        for (int nt = 0; nt < 4; nt++)
            #pragma unroll
            for (int q = 0; q < 4; q++) acc[mt][nt][q] = 0.f;

    float4 aR[4];
    uint2  bhR[2], blR[2];

#define LOADR(c_) do { \
    _Pragma("unroll") for (int it = 0; it < 4; it++) { \
        int idx = tid + it * 256; int row = idx >> 3, kq = idx & 7; \
        int grow = rowBase + row; \
        aR[it] = (grow < Nn) ? *(const float4*)(x + (size_t)grow * FIN + (c_) * 32 + kq * 4) \
                             : make_float4(0.f, 0.f, 0.f, 0.f); \
    } \
    _Pragma("unroll") for (int it = 0; it < 2; it++) { \
        int idx = tid + it * 256; int n = idx >> 3, j = idx & 7; \
        bhR[it] = g_wbh2[n * 128 + (c_) * 8 + j]; \
        blR[it] = g_wbl2[n * 128 + (c_) * 8 + j]; \
    } } while (0)

#define STS(s_) do { \
    __nv_bfloat16 (*Ah_)[ASTR] = PAH(s_); __nv_bfloat16 (*Al_)[ASTR] = PAL(s_); \
    __nv_bfloat16 (*Bh_)[ASTR] = PBH(s_); __nv_bfloat16 (*Bl_)[ASTR] = PBL(s_); \
    _Pragma("unroll") for (int it = 0; it < 4; it++) { \
        int idx = tid + it * 256; int row = idx >> 3, kq = idx & 7; \
        float4 v = aR[it]; \
        uint32_t h01 = pack_bf2(v.x, v.y), h23 = pack_bf2(v.z, v.w); \
        __nv_bfloat162 hh01 = *reinterpret_cast<__nv_bfloat162*>(&h01); \
        __nv_bfloat162 hh23 = *reinterpret_cast<__nv_bfloat162*>(&h23); \
        uint32_t l01 = pack_bf2(v.x - __bfloat162float(hh01.x), v.y - __bfloat162float(hh01.y)); \
        uint32_t l23 = pack_bf2(v.z - __bfloat162float(hh23.x), v.w - __bfloat162float(hh23.y)); \
        *(uint2*)&Ah_[row][kq * 4] = make_uint2(h01, h23); \
        *(uint2*)&Al_[row][kq * 4] = make_uint2(l01, l23); \
    } \
    _Pragma("unroll") for (int it = 0; it < 2; it++) { \
        int idx = tid + it * 256; int n = idx >> 3, j = idx & 7; \
        *(uint2*)&Bh_[n][j * 4] = bhR[it]; \
        *(uint2*)&Bl_[n][j * 4] = blR[it]; \
    } } while (0)

    LOADR(0);
    STS(0);
    __syncthreads();

    for (int c = 0; c < 16; c++) {
        int cur = c & 1;
        if (c < 15) LOADR(c + 1);          // gmem->reg prefetch overlaps compute
        {
            __nv_bfloat16 (*Ah_)[ASTR] = PAH(cur); __nv_bfloat16 (*Al_)[ASTR] = PAL(cur);
            __nv_bfloat16 (*Bh_)[ASTR] = PBH(cur); __nv_bfloat16 (*Bl_)[ASTR] = PBL(cur);
            #pragma unroll
            for (int kk = 0; kk < 2; kk++) {
                int kb = kk * 16;
                uint32_t aH[2][4], aL[2][4], bH[4][2], bL[4][2];
                #pragma unroll
                for (int mt = 0; mt < 2; mt++) {
                    int r0 = warpM * 32 + mt * 16 + g;
                    aH[mt][0] = *(const uint32_t*)&Ah_[r0    ][kb + tg * 2];
                    aH[mt][1] = *(const uint32_t*)&Ah_[r0 + 8][kb + tg * 2];
                    aH[mt][2] = *(const uint32_t*)&Ah_[r0    ][kb + tg * 2 + 8];
                    aH[mt][3] = *(const uint32_t*)&Ah_[r0 + 8][kb + tg * 2 + 8];
                    aL[mt][0] = *(const uint32_t*)&Al_[r0    ][kb + tg * 2];
                    aL[mt][1] = *(const uint32_t*)&Al_[r0 + 8][kb + tg * 2];
                    aL[mt][2] = *(const uint32_t*)&Al_[r0    ][kb + tg * 2 + 8];
                    aL[mt][3] = *(const uint32_t*)&Al_[r0 + 8][kb + tg * 2 + 8];
                }
                #pragma unroll
                for (int nt = 0; nt < 4; nt++) {
                    int n0 = warpN * 32 + nt * 8 + g;
                    bH[nt][0] = *(const uint32_t*)&Bh_[n0][kb + tg * 2];
                    bH[nt][1] = *(const uint32_t*)&Bh_[n0][kb + tg * 2 + 8];
                    bL[nt][0] = *(const uint32_t*)&Bl_[n0][kb + tg * 2];
                    bL[nt][1] = *(const uint32_t*)&Bl_[n0][kb + tg * 2 + 8];
                }
                #pragma unroll
                for (int mt = 0; mt < 2; mt++)
                    #pragma unroll
                    for (int nt = 0; nt < 4; nt++) {
                        MMA_BF16(acc[mt][nt], aH[mt], bH[nt]);
                        MMA_BF16(acc[mt][nt], aL[mt], bH[nt]);
                        MMA_BF16(acc[mt][nt], aH[mt], bL[nt]);
                    }
            }
        }
        if (c < 15) STS(cur ^ 1);          // write other buffer: no hazard
        __syncthreads();                   // single barrier per chunk
    }

    // epilogue: store h1 + fused alpha1 partial dots
    #pragma unroll
    for (int mt = 0; mt < 2; mt++) {
        int r = rowBase + warpM * 32 + mt * 16 + g;
        float ps0 = 0.f, pd0 = 0.f, ps1 = 0.f, pd1 = 0.f;
        #pragma unroll
        for (int nt = 0; nt < 4; nt++) {
            int cb = warpN * 32 + nt * 8 + tg * 2;
            if (r < Nn)
                *(float2*)(g_h1 + (size_t)r * FHID + cb) =
                    make_float2(acc[mt][nt][0], acc[mt][nt][1]);
            if (r + 8 < Nn)
                *(float2*)(g_h1 + (size_t)(r + 8) * FHID + cb) =
                    make_float2(acc[mt][nt][2], acc[mt][nt][3]);
            float a0s = __ldg(a_s + cb), a1s = __ldg(a_s + cb + 1);
            float a0d = __ldg(a_d + cb), a1d = __ldg(a_d + cb + 1);
            ps0 += acc[mt][nt][0] * a0s + acc[mt][nt][1] * a1s;
            pd0 += acc[mt][nt][0] * a0d + acc[mt][nt][1] * a1d;
            ps1 += acc[mt][nt][2] * a0s + acc[mt][nt][3] * a1s;
            pd1 += acc[mt][nt][2] * a0d + acc[mt][nt][3] * a1d;
        }
        #pragma unroll
        for (int o = 1; o <= 2; o <<= 1) {
            ps0 += __shfl_xor_sync(0xffffffffu, ps0, o);
            pd0 += __shfl_xor_sync(0xffffffffu, pd0, o);
            ps1 += __shfl_xor_sync(0xffffffffu, ps1, o);
            pd1 += __shfl_xor_sync(0xffffffffu, pd1, o);
        }
        if (tg == 0) {
            if (r < Nn)     { atomicAdd(&g_as1[r], ps0);     atomicAdd(&g_ad1[r], pd0); }
            if (r + 8 < Nn) { atomicAdd(&g_as1[r + 8], ps1); atomicAdd(&g_ad1[r + 8], pd1); }
        }
    }
#undef LOADR
#undef STS
}

// ---------------- layer-1 aggregation: warp per node, batched edges ----------
__global__ __launch_bounds__(256) void k_agg1(const float* __restrict__ b1) {
    int warp = (blockIdx.x * blockDim.x + threadIdx.x) >> 5;
    int lane = threadIdx.x & 31;
    if (warp >= Nn) return;
    int d = warp;
    int beg = __ldg(&g_off[d]), end = __ldg(&g_off[d + 1]);
    float add = g_ad1[d];

    // pass 1: per-node max (lanes over edges; also warms csr/as1 caches)
    float m = -3.402823e38f;
    for (int e = beg + lane; e < end; e += 32) {
        int s = __ldg(&g_csr_src[e]);
        s = (unsigned)s >= Nn ? 0 : s;
        m = fmaxf(m, __ldg(&g_as1[s]));
    }
    #pragma unroll
    for (int o = 16; o; o >>= 1) m = fmaxf(m, __shfl_xor_sync(0xffffffffu, m, o));
    m = leaky(m + add);   // leaky monotone: max of leaky = leaky of max

    // pass 2: 32-edge tiles; shuffled (s,w) -> high MLP, coalesced 256B rows
    float acc0 = 0.f, acc1 = 0.f, ssum = 0.f;
    for (int base = beg; base < end; base += 32) {
        int e = base + lane;
        int s_l = 0;
        float w_l = 0.f;
        if (e < end) {
            s_l = __ldg(&g_csr_src[e]);
            s_l = (unsigned)s_l >= Nn ? 0 : s_l;
            w_l = __expf(leaky(__ldg(&g_as1[s_l]) + add) - m);
        }
        ssum += w_l;
        int cnt = min(32, end - base);
        #pragma unroll 8
        for (int j = 0; j < cnt; j++) {
            int   s = __shfl_sync(0xffffffffu, s_l, j);
            float w = __shfl_sync(0xffffffffu, w_l, j);
            float2 hv = *(const float2*)(g_h1 + (size_t)s * FHID + 2 * lane);
            acc0 += w * hv.x;
            acc1 += w * hv.y;
        }
    }
    #pragma unroll
    for (int o = 16; o; o >>= 1) ssum += __shfl_xor_sync(0xffffffffu, ssum, o);

    float inv = 1.f / ssum;
    float v0 = fmaxf(acc0 * inv + b1[2 * lane], 0.f);
    float v1 = fmaxf(acc1 * inv + b1[2 * lane + 1], 0.f);
    *(float2*)(g_h1r + (size_t)d * FHID + 2 * lane) = make_float2(v0, v1);
}

// ---------------- GEMM2 + alpha2 fused ----------------
__global__ __launch_bounds__(128) void k_gemm2(const float* __restrict__ W2,
                                               const float* __restrict__ a_s,
                                               const float* __restrict__ a_d) {
    __shared__ float Ws[FHID * FOUT];
    __shared__ float s_as[FOUT], s_ad[FOUT];
    for (int t = threadIdx.x; t < FHID * FOUT; t += blockDim.x) Ws[t] = W2[t];
    if (threadIdx.x < FOUT) {
        s_as[threadIdx.x] = a_s[threadIdx.x];
        s_ad[threadIdx.x] = a_d[threadIdx.x];
    }
    __syncthreads();
    int i = blockIdx.x * blockDim.x + threadIdx.x;
    if (i >= Nn) return;
    float acc[FOUT];
    #pragma unroll
    for (int c = 0; c < FOUT; c++) acc[c] = 0.f;
    const float4* hr = (const float4*)(g_h1r + (size_t)i * FHID);
    #pragma unroll
    for (int k4 = 0; k4 < FHID / 4; k4++) {
        float4 xv = hr[k4];
        const float* w0 = &Ws[(k4 * 4 + 0) * FOUT];
        const float* w1 = &Ws[(k4 * 4 + 1) * FOUT];
        const float* w2 = &Ws[(k4 * 4 + 2) * FOUT];
        const float* w3 = &Ws[(k4 * 4 + 3) * FOUT];
        #pragma unroll
        for (int c = 0; c < FOUT; c++)
            acc[c] += xv.x * w0[c] + xv.y * w1[c] + xv.z * w2[c] + xv.w * w3[c];
    }
    float s = 0.f, dd = 0.f;
    #pragma unroll
    for (int c = 0; c < FOUT; c++) { s += acc[c] * s_as[c]; dd += acc[c] * s_ad[c]; }
    float* orow = g_h2 + (size_t)i * FOUT;
    #pragma unroll
    for (int c = 0; c < FOUT; c += 4)
        *(float4*)(orow + c) = make_float4(acc[c], acc[c + 1], acc[c + 2], acc[c + 3]);
    g_as2[i] = s;
    g_ad2[i] = dd;
}

// ---------------- layer-2 aggregation + bias + log_softmax -------------------
__global__ __launch_bounds__(256) void k_agg2(const float* __restrict__ b2,
                                              float* __restrict__ out) {
    int warp = (blockIdx.x * blockDim.x + threadIdx.x) >> 5;
    int lane = threadIdx.x & 31;
    if (warp >= Nn) return;
    int d = warp;
    int beg = __ldg(&g_off[d]), end = __ldg(&g_off[d + 1]);
    float add = g_ad2[d];

    float m = -3.402823e38f;
    for (int e = beg + lane; e < end; e += 32) {
        int s = __ldg(&g_csr_src[e]);
        s = (unsigned)s >= Nn ? 0 : s;
        m = fmaxf(m, __ldg(&g_as2[s]));
    }
    #pragma unroll
    for (int o = 16; o; o >>= 1) m = fmaxf(m, __shfl_xor_sync(0xffffffffu, m, o));
    m = leaky(m + add);

    float acc0 = 0.f, acc1 = 0.f, ssum = 0.f;
    for (int base = beg; base < end; base += 32) {
        int e = base + lane;
        int s_l = 0;
        float w_l = 0.f;
        if (e < end) {
            s_l = __ldg(&g_csr_src[e]);
            s_l = (unsigned)s_l >= Nn ? 0 : s_l;
            w_l = __expf(leaky(__ldg(&g_as2[s_l]) + add) - m);
        }
        ssum += w_l;
        int cnt = min(32, end - base);
        #pragma unroll 8
        for (int j = 0; j < cnt; j++) {
            int   s = __shfl_sync(0xffffffffu, s_l, j);
            float w = __shfl_sync(0xffffffffu, w_l, j);
            const float* hrow = g_h2 + (size_t)s * FOUT;
            acc0 += w * hrow[lane];
            if (lane < FOUT - 32) acc1 += w * hrow[32 + lane];
        }
    }
    #pragma unroll
    for (int o = 16; o; o >>= 1) ssum += __shfl_xor_sync(0xffffffffu, ssum, o);

    float inv = 1.f / ssum;
    float v0 = acc0 * inv + b2[lane];
    float v1 = (lane < FOUT - 32) ? acc1 * inv + b2[32 + lane] : -3.402823e38f;

    // log_softmax over the 40 values held by the warp
    float mx = fmaxf(v0, v1);
    #pragma unroll
    for (int o = 16; o; o >>= 1) mx = fmaxf(mx, __shfl_xor_sync(0xffffffffu, mx, o));
    float se = __expf(v0 - mx) + ((lane < FOUT - 32) ? __expf(v1 - mx) : 0.f);
    #pragma unroll
    for (int o = 16; o; o >>= 1) se += __shfl_xor_sync(0xffffffffu, se, o);
    float lse = logf(se);

    float* orow = out + (size_t)d * FOUT;
    orow[lane] = v0 - mx - lse;
    if (lane < FOUT - 32) orow[32 + lane] = v1 - mx - lse;
}

// ---------------- launcher ----------------
extern "C" void kernel_launch(void* const* d_in, const int* in_sizes, int n_in,
                              void* d_out, int out_size) {
    const float* x      = (const float*)d_in[0];
    const void*  ei     = d_in[1];
    const float* W1     = (const float*)d_in[2];
    const float* a_src1 = (const float*)d_in[3];
    const float* a_dst1 = (const float*)d_in[4];
    const float* b1     = (const float*)d_in[5];
    const float* W2     = (const float*)d_in[6];
    const float* a_src2 = (const float*)d_in[7];
    const float* a_dst2 = (const float*)d_in[8];
    const float* b2     = (const float*)d_in[9];
    float* out = (float*)d_out;

    // defensive re-apply (idempotent, not a stream op; capture-legal)
    cudaFuncSetAttribute(k_gemm1_mma,
                         cudaFuncAttributeMaxDynamicSharedMemorySize, SMTOT);

    // detect dtype on main stream, then fork CSR chain onto side stream
    k_detect<<<1, 256>>>((const int2*)ei);
    cudaEventRecord(g_evFork, 0);
    cudaStreamWaitEvent(g_s2, g_evFork, 0);

    // side stream: CSR build (independent of GEMM1)
    k_init_cnt<<<(Nn + 255) / 256, 256, 0, g_s2>>>();
    k_hist<<<(Ee + 255) / 256, 256, 0, g_s2>>>(ei);
    k_scan1<<<SCAN_NBLK, SCAN_BS, 0, g_s2>>>();
    k_scan2<<<1, 32, 0, g_s2>>>();
    k_scan3<<<(Nn + 255) / 256, 256, 0, g_s2>>>();
    k_scatter<<<(EN + 255) / 256, 256, 0, g_s2>>>(ei);
    cudaEventRecord(g_evJoin, g_s2);

    // main stream: W1 convert + init, then GEMM1 with fused alpha1
    k_convW<<<(Nn + 255) / 256, 256>>>(W1);
    k_gemm1_mma<<<TILES, 256, SMTOT>>>(x, a_src1, a_dst1);

    // join: agg1 needs CSR + gemm1 results
    cudaStreamWaitEvent(0, g_evJoin, 0);
    k_agg1<<<(Nn * 32 + 255) / 256, 256>>>(b1);

    // layer 2
    k_gemm2<<<(Nn + 127) / 128, 128>>>(W2, a_src2, a_dst2);
    k_agg2<<<(Nn * 32 + 255) / 256, 256>>>(b2, out);
}

// round 13
// speedup vs baseline: 1.2111x; 1.0184x over previous
#include <cuda_runtime.h>
#include <cuda_bf16.h>
#include <math.h>
#include <stdint.h>

// ---------------- problem constants ----------------
#define Nn   100000
#define Ee   1600000
#define EN   (Ee + Nn)          // edges incl. self loops = 1,700,000
#define FIN  512
#define FHID 64
#define FOUT 40
#define NEG_SLOPE 0.2f
#define TILES ((Nn + 127) / 128)   // 782

// ---------------- device scratch (no dynamic alloc allowed) ----------------
__device__ __align__(16) float g_h1 [(size_t)Nn * FHID];   // x@W1
__device__ __align__(16) float g_h1r[(size_t)Nn * FHID];   // relu(layer1 out)
__device__ __align__(16) float g_h2 [(size_t)Nn * FOUT];   // h1r@W2
__device__ float g_as1[Nn], g_ad1[Nn];
__device__ float g_as2[Nn], g_ad2[Nn];
__device__ int   g_cnt[Nn];
__device__ int   g_off[Nn + 1];
__device__ int   g_cursor[Nn];
__device__ int   g_csr_src[EN];
__device__ int   g_is64;
// W1 pre-converted: [n][k] K-contiguous bf16 hi/lo, stored as uint2 = 4 bf16 along k
__device__ __align__(16) uint2 g_wbh2[64 * 128];
__device__ __align__(16) uint2 g_wbl2[64 * 128];

#define SCAN_BS   1024
#define SCAN_NBLK ((Nn + SCAN_BS - 1) / SCAN_BS)   // 98
__device__ int g_partials[SCAN_NBLK];

__device__ __forceinline__ uint32_t pack_bf2(float a, float b) {
    __nv_bfloat162 t = __floats2bfloat162_rn(a, b);
    return *reinterpret_cast<uint32_t*>(&t);
}
__device__ __forceinline__ float leaky(float z) { return z > 0.f ? z : NEG_SLOPE * z; }

// mma.sync m16n8k16 row.col f32.bf16.bf16.f32 (sm_80+ PTX, valid on sm_100)
#define MMA_BF16(c, a, b) \
    asm volatile("mma.sync.aligned.m16n8k16.row.col.f32.bf16.bf16.f32 " \
        "{%0,%1,%2,%3}, {%4,%5,%6,%7}, {%8,%9}, {%0,%1,%2,%3};" \
        : "+f"((c)[0]), "+f"((c)[1]), "+f"((c)[2]), "+f"((c)[3]) \
        : "r"((a)[0]), "r"((a)[1]), "r"((a)[2]), "r"((a)[3]), "r"((b)[0]), "r"((b)[1]))

// ldmatrix x4: four 8x8 b16 tiles; lane groups 0-7/8-15/16-23/24-31 give row addrs
#define LDSM_X4(r0, r1, r2, r3, addr) \
    asm volatile("ldmatrix.sync.aligned.m8n8.x4.shared.b16 {%0,%1,%2,%3}, [%4];" \
        : "=r"(r0), "=r"(r1), "=r"(r2), "=r"(r3) : "r"(addr))

// ---------------- GEMM1 smem sizing (needed by initializer below) ------------
#define ASTR 40                           // 32 + 8 pad bf16
#define ABY  (128 * ASTR * 2)             // 10240 B per A buffer
#define BBY  (64 * ASTR * 2)              // 5120 B per B buffer
#define STAGEB (2 * ABY + 2 * BBY)        // 30720 B per stage
#define SMTOT  (2 * STAGEB)               // 61440 B dynamic smem

__global__ __launch_bounds__(256) void k_gemm1_mma(const float* __restrict__ x,
                                                   const float* __restrict__ a_s,
                                                   const float* __restrict__ a_d);

// ---------------- streams + one-time func config (pre-main) ----------------
static cudaStream_t g_s2;
static cudaEvent_t  g_evFork, g_evJoin;
static struct _StreamInit {
    _StreamInit() {
        cudaStreamCreateWithFlags(&g_s2, cudaStreamNonBlocking);
        cudaEventCreateWithFlags(&g_evFork, cudaEventDisableTiming);
        cudaEventCreateWithFlags(&g_evJoin, cudaEventDisableTiming);
        cudaFuncSetAttribute(k_gemm1_mma,
                             cudaFuncAttributeMaxDynamicSharedMemorySize, SMTOT);
    }
} g_streamInit;

__device__ __forceinline__ int load_edge(const void* ei, long long idx, int is64) {
    int v;
    if (is64) v = (int)((const long long*)ei)[idx];
    else      v = ((const int*)ei)[idx];
    v = v < 0 ? 0 : (v >= Nn ? Nn - 1 : v);
    return v;
}

// ------------- head kernel: dtype detect + cnt init + W1 convert + zeroing ---
__global__ void k_head(const int2* __restrict__ ep, const float* __restrict__ W1) {
    int idx = blockIdx.x * blockDim.x + threadIdx.x;
    // block 0: dtype detection (int64 -> all hi words of first 1024 pairs are 0)
    if (blockIdx.x == 0) {
        __shared__ int flag;
        if (threadIdx.x == 0) flag = 0;
        __syncthreads();
        int nz = 0;
        for (int i = threadIdx.x; i < 1024; i += blockDim.x)
            if (ep[i].y != 0) nz = 1;
        if (nz) atomicOr(&flag, 1);
        __syncthreads();
        if (threadIdx.x == 0) g_is64 = (flag == 0) ? 1 : 0;
    }
    if (idx < 64 * 128) {   // W1 hi/lo convert: n*128 + k4
        int n = idx >> 7, k4 = idx & 127;
        float f[4], lo[4];
        #pragma unroll
        for (int j = 0; j < 4; j++) {
            f[j] = W1[(size_t)(k4 * 4 + j) * FHID + n];
            __nv_bfloat16 hb = __float2bfloat16(f[j]);
            lo[j] = f[j] - __bfloat162float(hb);
        }
        g_wbh2[idx] = make_uint2(pack_bf2(f[0], f[1]), pack_bf2(f[2], f[3]));
        g_wbl2[idx] = make_uint2(pack_bf2(lo[0], lo[1]), pack_bf2(lo[2], lo[3]));
    }
    if (idx < Nn) {
        g_cnt[idx] = 1;         // self loop pre-counted
        g_as1[idx] = 0.f;
        g_ad1[idx] = 0.f;
    }
}

// ---------------- CSR build ----------------
__global__ void k_hist(const void* __restrict__ ei) {
    int i = blockIdx.x * blockDim.x + threadIdx.x;
    int is64 = g_is64;
    if (i < Ee) {
        int d = load_edge(ei, (long long)Ee + i, is64);
        atomicAdd(&g_cnt[d], 1);
    }
}
__global__ void k_scan1() {
    __shared__ int sm[SCAN_BS];
    int tid = threadIdx.x;
    int i = blockIdx.x * SCAN_BS + tid;
    int v = (i < Nn) ? g_cnt[i] : 0;
    sm[tid] = v;
    __syncthreads();
    #pragma unroll
    for (int off = 1; off < SCAN_BS; off <<= 1) {
        int t = (tid >= off) ? sm[tid - off] : 0;
        __syncthreads();
        sm[tid] += t;
        __syncthreads();
    }
    int incl = sm[tid];
    if (i < Nn) g_off[i] = incl - v;
    if (tid == SCAN_BS - 1) g_partials[blockIdx.x] = incl;
}
__global__ void k_scan2() {
    if (threadIdx.x == 0 && blockIdx.x == 0) {
        int run = 0;
        for (int b = 0; b < SCAN_NBLK; b++) {
            int t = g_partials[b];
            g_partials[b] = run;
            run += t;
        }
    }
}
__global__ void k_scan3() {
    int i = blockIdx.x * blockDim.x + threadIdx.x;
    if (i < Nn) {
        int o = g_off[i] + g_partials[i / SCAN_BS];
        g_off[i] = o;
        g_cursor[i] = o;
    }
    if (i == 0) g_off[Nn] = EN;
}
__global__ void k_scatter(const void* __restrict__ ei) {
    int i = blockIdx.x * blockDim.x + threadIdx.x;
    if (i >= EN) return;
    int is64 = g_is64;
    int s, d;
    if (i < Ee) {
        s = load_edge(ei, i, is64);
        d = load_edge(ei, (long long)Ee + i, is64);
    } else {
        s = d = i - Ee;
    }
    int pos = atomicAdd(&g_cursor[d], 1);
    if (pos >= 0 && pos < EN) g_csr_src[pos] = s;
}

// ---------------- GEMM1: mma.sync bf16 hi/lo, double-buffered + ldmatrix -----
__global__ __launch_bounds__(256) void k_gemm1_mma(const float* __restrict__ x,
                                                   const float* __restrict__ a_s,
                                                   const float* __restrict__ a_d) {
    extern __shared__ char dynsm[];
    int tid = threadIdx.x, wid = tid >> 5, lane = tid & 31;
    int warpM = wid & 3, warpN = wid >> 2;     // 4 x 2
    int rowBase = blockIdx.x * 128;
    int g = lane >> 2, tg = lane & 3;

#define PAH(s) ((__nv_bfloat16(*)[ASTR])(dynsm + (s) * STAGEB))
#define PAL(s) ((__nv_bfloat16(*)[ASTR])(dynsm + (s) * STAGEB + ABY))
#define PBH(s) ((__nv_bfloat16(*)[ASTR])(dynsm + (s) * STAGEB + 2 * ABY))
#define PBL(s) ((__nv_bfloat16(*)[ASTR])(dynsm + (s) * STAGEB + 2 * ABY + BBY))

    uint32_t smemBase = (uint32_t)__cvta_generic_to_shared(dynsm);
    // lane-dependent ldmatrix byte offsets (within a tile, before kb/stage)
    // A m16k16 x4: lanes 0-15 -> rows +0..15 col +0; 16-31 -> rows +0..15 col +8
    uint32_t aLaneOff = (uint32_t)(((warpM * 32 + (lane & 15)) * ASTR + ((lane >> 4) * 8)) * 2);
    // B two-n8k16-tiles x4: g0 rows +0..7 col 0; g1 rows +0..7 col 8; g2 +8..15 col 0; g3 +8..15 col 8
    uint32_t bLaneOff = (uint32_t)(((warpN * 32 + ((lane >> 4) * 8) + (lane & 7)) * ASTR
                                    + (((lane >> 3) & 1) * 8)) * 2);

    float acc[2][4][4];
    #pragma unroll
    for (int mt = 0; mt < 2; mt++)
        #pragma unroll
        for (int nt = 0; nt < 4; nt++)
            #pragma unroll
            for (int q = 0; q < 4; q++) acc[mt][nt][q] = 0.f;

    float4 aR[4];
    uint2  bhR[2], blR[2];

#define LOADR(c_) do { \
    _Pragma("unroll") for (int it = 0; it < 4; it++) { \
        int idx = tid + it * 256; int row = idx >> 3, kq = idx & 7; \
        int grow = rowBase + row; \
        aR[it] = (grow < Nn) ? *(const float4*)(x + (size_t)grow * FIN + (c_) * 32 + kq * 4) \
                             : make_float4(0.f, 0.f, 0.f, 0.f); \
    } \
    _Pragma("unroll") for (int it = 0; it < 2; it++) { \
        int idx = tid + it * 256; int n = idx >> 3, j = idx & 7; \
        bhR[it] = g_wbh2[n * 128 + (c_) * 8 + j]; \
        blR[it] = g_wbl2[n * 128 + (c_) * 8 + j]; \
    } } while (0)

#define STS(s_) do { \
    __nv_bfloat16 (*Ah_)[ASTR] = PAH(s_); __nv_bfloat16 (*Al_)[ASTR] = PAL(s_); \
    __nv_bfloat16 (*Bh_)[ASTR] = PBH(s_); __nv_bfloat16 (*Bl_)[ASTR] = PBL(s_); \
    _Pragma("unroll") for (int it = 0; it < 4; it++) { \
        int idx = tid + it * 256; int row = idx >> 3, kq = idx & 7; \
        float4 v = aR[it]; \
        uint32_t h01 = pack_bf2(v.x, v.y), h23 = pack_bf2(v.z, v.w); \
        __nv_bfloat162 hh01 = *reinterpret_cast<__nv_bfloat162*>(&h01); \
        __nv_bfloat162 hh23 = *reinterpret_cast<__nv_bfloat162*>(&h23); \
        uint32_t l01 = pack_bf2(v.x - __bfloat162float(hh01.x), v.y - __bfloat162float(hh01.y)); \
        uint32_t l23 = pack_bf2(v.z - __bfloat162float(hh23.x), v.w - __bfloat162float(hh23.y)); \
        *(uint2*)&Ah_[row][kq * 4] = make_uint2(h01, h23); \
        *(uint2*)&Al_[row][kq * 4] = make_uint2(l01, l23); \
    } \
    _Pragma("unroll") for (int it = 0; it < 2; it++) { \
        int idx = tid + it * 256; int n = idx >> 3, j = idx & 7; \
        *(uint2*)&Bh_[n][j * 4] = bhR[it]; \
        *(uint2*)&Bl_[n][j * 4] = blR[it]; \
    } } while (0)

    LOADR(0);
    STS(0);
    __syncthreads();

    for (int c = 0; c < 16; c++) {
        int cur = c & 1;
        if (c < 15) LOADR(c + 1);          // gmem->reg prefetch overlaps compute
        {
            uint32_t sAh = smemBase + cur * STAGEB;
            uint32_t sAl = sAh + ABY;
            uint32_t sBh = sAh + 2 * ABY;
            uint32_t sBl = sBh + BBY;
            #pragma unroll
            for (int kk = 0; kk < 2; kk++) {
                uint32_t kbB = (uint32_t)(kk * 16 * 2);   // kb bytes
                uint32_t aOff = aLaneOff + kbB;
                uint32_t bOff = bLaneOff + kbB;
                uint32_t aH[2][4], aL[2][4], bH[4][2], bL[4][2];
                LDSM_X4(aH[0][0], aH[0][1], aH[0][2], aH[0][3], sAh + aOff);
                LDSM_X4(aH[1][0], aH[1][1], aH[1][2], aH[1][3], sAh + aOff + 16 * ASTR * 2);
                LDSM_X4(aL[0][0], aL[0][1], aL[0][2], aL[0][3], sAl + aOff);
                LDSM_X4(aL[1][0], aL[1][1], aL[1][2], aL[1][3], sAl + aOff + 16 * ASTR * 2);
                LDSM_X4(bH[0][0], bH[0][1], bH[1][0], bH[1][1], sBh + bOff);
                LDSM_X4(bH[2][0], bH[2][1], bH[3][0], bH[3][1], sBh + bOff + 16 * ASTR * 2);
                LDSM_X4(bL[0][0], bL[0][1], bL[1][0], bL[1][1], sBl + bOff);
                LDSM_X4(bL[2][0], bL[2][1], bL[3][0], bL[3][1], sBl + bOff + 16 * ASTR * 2);
                #pragma unroll
                for (int mt = 0; mt < 2; mt++)
                    #pragma unroll
                    for (int nt = 0; nt < 4; nt++) {
                        MMA_BF16(acc[mt][nt], aH[mt], bH[nt]);
                        MMA_BF16(acc[mt][nt], aL[mt], bH[nt]);
                        MMA_BF16(acc[mt][nt], aH[mt], bL[nt]);
                    }
            }
        }
        if (c < 15) STS(cur ^ 1);          // write other buffer: no hazard
        __syncthreads();                   // single barrier per chunk
    }

    // epilogue: store h1 + fused alpha1 partial dots
    #pragma unroll
    for (int mt = 0; mt < 2; mt++) {
        int r = rowBase + warpM * 32 + mt * 16 + g;
        float ps0 = 0.f, pd0 = 0.f, ps1 = 0.f, pd1 = 0.f;
        #pragma unroll
        for (int nt = 0; nt < 4; nt++) {
            int cb = warpN * 32 + nt * 8 + tg * 2;
            if (r < Nn)
                *(float2*)(g_h1 + (size_t)r * FHID + cb) =
                    make_float2(acc[mt][nt][0], acc[mt][nt][1]);
            if (r + 8 < Nn)
                *(float2*)(g_h1 + (size_t)(r + 8) * FHID + cb) =
                    make_float2(acc[mt][nt][2], acc[mt][nt][3]);
            float a0s = __ldg(a_s + cb), a1s = __ldg(a_s + cb + 1);
            float a0d = __ldg(a_d + cb), a1d = __ldg(a_d + cb + 1);
            ps0 += acc[mt][nt][0] * a0s + acc[mt][nt][1] * a1s;
            pd0 += acc[mt][nt][0] * a0d + acc[mt][nt][1] * a1d;
            ps1 += acc[mt][nt][2] * a0s + acc[mt][nt][3] * a1s;
            pd1 += acc[mt][nt][2] * a0d + acc[mt][nt][3] * a1d;
        }
        #pragma unroll
        for (int o = 1; o <= 2; o <<= 1) {
            ps0 += __shfl_xor_sync(0xffffffffu, ps0, o);
            pd0 += __shfl_xor_sync(0xffffffffu, pd0, o);
            ps1 += __shfl_xor_sync(0xffffffffu, ps1, o);
            pd1 += __shfl_xor_sync(0xffffffffu, pd1, o);
        }
        if (tg == 0) {
            if (r < Nn)     { atomicAdd(&g_as1[r], ps0);     atomicAdd(&g_ad1[r], pd0); }
            if (r + 8 < Nn) { atomicAdd(&g_as1[r + 8], ps1); atomicAdd(&g_ad1[r + 8], pd1); }
        }
    }
#undef LOADR
#undef STS
}

// ---------------- layer-1 aggregation: warp per node, batched edges ----------
__global__ __launch_bounds__(256) void k_agg1(const float* __restrict__ b1) {
    int warp = (blockIdx.x * blockDim.x + threadIdx.x) >> 5;
    int lane = threadIdx.x & 31;
    if (warp >= Nn) return;
    int d = warp;
    int beg = __ldg(&g_off[d]), end = __ldg(&g_off[d + 1]);
    float add = g_ad1[d];

    // pass 1: per-node max (lanes over edges; also warms csr/as1 caches)
    float m = -3.402823e38f;
    for (int e = beg + lane; e < end; e += 32) {
        int s = __ldg(&g_csr_src[e]);
        s = (unsigned)s >= Nn ? 0 : s;
        m = fmaxf(m, __ldg(&g_as1[s]));
    }
    #pragma unroll
    for (int o = 16; o; o >>= 1) m = fmaxf(m, __shfl_xor_sync(0xffffffffu, m, o));
    m = leaky(m + add);   // leaky monotone: max of leaky = leaky of max

    // pass 2: 32-edge tiles; shuffled (s,w) -> high MLP, coalesced 256B rows
    float acc0 = 0.f, acc1 = 0.f, ssum = 0.f;
    for (int base = beg; base < end; base += 32) {
        int e = base + lane;
        int s_l = 0;
        float w_l = 0.f;
        if (e < end) {
            s_l = __ldg(&g_csr_src[e]);
            s_l = (unsigned)s_l >= Nn ? 0 : s_l;
            w_l = __expf(leaky(__ldg(&g_as1[s_l]) + add) - m);
        }
        ssum += w_l;
        int cnt = min(32, end - base);
        #pragma unroll 8
        for (int j = 0; j < cnt; j++) {
            int   s = __shfl_sync(0xffffffffu, s_l, j);
            float w = __shfl_sync(0xffffffffu, w_l, j);
            float2 hv = *(const float2*)(g_h1 + (size_t)s * FHID + 2 * lane);
            acc0 += w * hv.x;
            acc1 += w * hv.y;
        }
    }
    #pragma unroll
    for (int o = 16; o; o >>= 1) ssum += __shfl_xor_sync(0xffffffffu, ssum, o);

    float inv = 1.f / ssum;
    float v0 = fmaxf(acc0 * inv + b1[2 * lane], 0.f);
    float v1 = fmaxf(acc1 * inv + b1[2 * lane + 1], 0.f);
    *(float2*)(g_h1r + (size_t)d * FHID + 2 * lane) = make_float2(v0, v1);
}

// ---------------- GEMM2 + alpha2 fused ----------------
__global__ __launch_bounds__(128) void k_gemm2(const float* __restrict__ W2,
                                               const float* __restrict__ a_s,
                                               const float* __restrict__ a_d) {
    __shared__ float Ws[FHID * FOUT];
    __shared__ float s_as[FOUT], s_ad[FOUT];
    for (int t = threadIdx.x; t < FHID * FOUT; t += blockDim.x) Ws[t] = W2[t];
    if (threadIdx.x < FOUT) {
        s_as[threadIdx.x] = a_s[threadIdx.x];
        s_ad[threadIdx.x] = a_d[threadIdx.x];
    }
    __syncthreads();
    int i = blockIdx.x * blockDim.x + threadIdx.x;
    if (i >= Nn) return;
    float acc[FOUT];
    #pragma unroll
    for (int c = 0; c < FOUT; c++) acc[c] = 0.f;
    const float4* hr = (const float4*)(g_h1r + (size_t)i * FHID);
    #pragma unroll
    for (int k4 = 0; k4 < FHID / 4; k4++) {
        float4 xv = hr[k4];
        const float* w0 = &Ws[(k4 * 4 + 0) * FOUT];
        const float* w1 = &Ws[(k4 * 4 + 1) * FOUT];
        const float* w2 = &Ws[(k4 * 4 + 2) * FOUT];
        const float* w3 = &Ws[(k4 * 4 + 3) * FOUT];
        #pragma unroll
        for (int c = 0; c < FOUT; c++)
            acc[c] += xv.x * w0[c] + xv.y * w1[c] + xv.z * w2[c] + xv.w * w3[c];
    }
    float s = 0.f, dd = 0.f;
    #pragma unroll
    for (int c = 0; c < FOUT; c++) { s += acc[c] * s_as[c]; dd += acc[c] * s_ad[c]; }
    float* orow = g_h2 + (size_t)i * FOUT;
    #pragma unroll
    for (int c = 0; c < FOUT; c += 4)
        *(float4*)(orow + c) = make_float4(acc[c], acc[c + 1], acc[c + 2], acc[c + 3]);
    g_as2[i] = s;
    g_ad2[i] = dd;
}

// ---------------- layer-2 aggregation + bias + log_softmax -------------------
__global__ __launch_bounds__(256) void k_agg2(const float* __restrict__ b2,
                                              float* __restrict__ out) {
    int warp = (blockIdx.x * blockDim.x + threadIdx.x) >> 5;
    int lane = threadIdx.x & 31;
    if (warp >= Nn) return;
    int d = warp;
    int beg = __ldg(&g_off[d]), end = __ldg(&g_off[d + 1]);
    float add = g_ad2[d];

    float m = -3.402823e38f;
    for (int e = beg + lane; e < end; e += 32) {
        int s = __ldg(&g_csr_src[e]);
        s = (unsigned)s >= Nn ? 0 : s;
        m = fmaxf(m, __ldg(&g_as2[s]));
    }
    #pragma unroll
    for (int o = 16; o; o >>= 1) m = fmaxf(m, __shfl_xor_sync(0xffffffffu, m, o));
    m = leaky(m + add);

    float acc0 = 0.f, acc1 = 0.f, ssum = 0.f;
    for (int base = beg; base < end; base += 32) {
        int e = base + lane;
        int s_l = 0;
        float w_l = 0.f;
        if (e < end) {
            s_l = __ldg(&g_csr_src[e]);
            s_l = (unsigned)s_l >= Nn ? 0 : s_l;
            w_l = __expf(leaky(__ldg(&g_as2[s_l]) + add) - m);
        }
        ssum += w_l;
        int cnt = min(32, end - base);
        #pragma unroll 8
        for (int j = 0; j < cnt; j++) {
            int   s = __shfl_sync(0xffffffffu, s_l, j);
            float w = __shfl_sync(0xffffffffu, w_l, j);
            const float* hrow = g_h2 + (size_t)s * FOUT;
            acc0 += w * hrow[lane];
            if (lane < FOUT - 32) acc1 += w * hrow[32 + lane];
        }
    }
    #pragma unroll
    for (int o = 16; o; o >>= 1) ssum += __shfl_xor_sync(0xffffffffu, ssum, o);

    float inv = 1.f / ssum;
    float v0 = acc0 * inv + b2[lane];
    float v1 = (lane < FOUT - 32) ? acc1 * inv + b2[32 + lane] : -3.402823e38f;

    // log_softmax over the 40 values held by the warp
    float mx = fmaxf(v0, v1);
    #pragma unroll
    for (int o = 16; o; o >>= 1) mx = fmaxf(mx, __shfl_xor_sync(0xffffffffu, mx, o));
    float se = __expf(v0 - mx) + ((lane < FOUT - 32) ? __expf(v1 - mx) : 0.f);
    #pragma unroll
    for (int o = 16; o; o >>= 1) se += __shfl_xor_sync(0xffffffffu, se, o);
    float lse = logf(se);

    float* orow = out + (size_t)d * FOUT;
    orow[lane] = v0 - mx - lse;
    if (lane < FOUT - 32) orow[32 + lane] = v1 - mx - lse;
}

// ---------------- launcher ----------------
extern "C" void kernel_launch(void* const* d_in, const int* in_sizes, int n_in,
                              void* d_out, int out_size) {
    const float* x      = (const float*)d_in[0];
    const void*  ei     = d_in[1];
    const float* W1     = (const float*)d_in[2];
    const float* a_src1 = (const float*)d_in[3];
    const float* a_dst1 = (const float*)d_in[4];
    const float* b1     = (const float*)d_in[5];
    const float* W2     = (const float*)d_in[6];
    const float* a_src2 = (const float*)d_in[7];
    const float* a_dst2 = (const float*)d_in[8];
    const float* b2     = (const float*)d_in[9];
    float* out = (float*)d_out;

    // defensive re-apply (idempotent, not a stream op; capture-legal)
    cudaFuncSetAttribute(k_gemm1_mma,
                         cudaFuncAttributeMaxDynamicSharedMemorySize, SMTOT);

    // head: dtype detect + cnt init + W1 convert + alpha zeroing, then fork
    k_head<<<(Nn + 255) / 256, 256>>>((const int2*)ei, W1);
    cudaEventRecord(g_evFork, 0);
    cudaStreamWaitEvent(g_s2, g_evFork, 0);

    // side stream: CSR build (independent of GEMM1)
    k_hist<<<(Ee + 255) / 256, 256, 0, g_s2>>>(ei);
    k_scan1<<<SCAN_NBLK, SCAN_BS, 0, g_s2>>>();
    k_scan2<<<1, 32, 0, g_s2>>>();
    k_scan3<<<(Nn + 255) / 256, 256, 0, g_s2>>>();
    k_scatter<<<(EN + 255) / 256, 256, 0, g_s2>>>(ei);
    cudaEventRecord(g_evJoin, g_s2);

    // main stream: GEMM1 with fused alpha1
    k_gemm1_mma<<<TILES, 256, SMTOT>>>(x, a_src1, a_dst1);

    // join: agg1 needs CSR + gemm1 results
    cudaStreamWaitEvent(0, g_evJoin, 0);
    k_agg1<<<(Nn * 32 + 255) / 256, 256>>>(b1);

    // layer 2
    k_gemm2<<<(Nn + 127) / 128, 128>>>(W2, a_src2, a_dst2);
    k_agg2<<<(Nn * 32 + 255) / 256, 256>>>(b2, out);
}